// round 2
// baseline (speedup 1.0000x reference)
#include <cuda_runtime.h>
#include <cstdint>
#include <cstddef>

// Problem constants (fixed by setup_inputs)
#define N_ 8
#define C_ 256
#define H_ 64
#define W_ 64
#define A_ 9
#define BS_ 8
#define F_ 8
#define K_ 64
#define M_ (A_*N_*K_)   // 4608

// Scratch (static device globals; no runtime allocation)
__device__ float g_regp[4 * N_*A_*F_*F_];      // conv partials (4 c-quarters)
__device__ float g_featT[(size_t)N_*H_*W_*C_]; // NHWC transposed feature
__device__ float g_roisb[(size_t)M_*C_];       // sampled rois_feature_b
__device__ float g_tmp[(size_t)M_*C_];         // intermediate rois output

// ---------------------------------------------------------------------------
// Kernel 1 (fused): blocks [0,8192): NCHW->NHWC transpose
//                   blocks [8192,8448): stride-8 8x8 VALID conv partials
// Conv: block b = (n, fy, cq). warp = fx. lane = (ky, cs): ky=lane>>2, cs=lane&3.
// Each lane accumulates acc[9] over its 64-channel quarter slice (16 c-iters,
// 8 kx per iter via two float4 loads = exactly one 32B sector per operand).
// 5-shfl reduce per aa, lane 0 stores the partial. No smem, no atomics.
// ---------------------------------------------------------------------------
__global__ __launch_bounds__(256)
void fused_tc_kernel(const float* __restrict__ feat, const float* __restrict__ Wreg) {
    if (blockIdx.x < 8192) {
        // ---- transpose role ----
        __shared__ float tile[32][33];
        int b   = blockIdx.x;
        int hwt = b & 127;
        int ct  = (b >> 7) & 7;
        int n   = b >> 10;
        int tx  = threadIdx.x & 31;
        int ty  = threadIdx.x >> 5;
        const float* src = feat + (size_t)n * C_ * H_ * W_;
        float* dst = g_featT + (size_t)n * H_ * W_ * C_;
        #pragma unroll
        for (int r = 0; r < 4; r++)
            tile[ty + r*8][tx] = src[(size_t)(ct*32 + ty + r*8) * 4096 + hwt*32 + tx];
        __syncthreads();
        #pragma unroll
        for (int r = 0; r < 4; r++)
            dst[(size_t)(hwt*32 + ty + r*8) * 256 + ct*32 + tx] = tile[tx][ty + r*8];
    } else {
        // ---- conv role ----
        int b    = blockIdx.x - 8192;   // 0..255
        int cq   = b & 3;
        int fyn  = b >> 2;              // 0..63
        int fy   = fyn & 7;
        int n    = fyn >> 3;
        int fx   = threadIdx.x >> 5;    // warp id = fx
        int lane = threadIdx.x & 31;
        int ky   = lane >> 2;
        int cs   = lane & 3;

        float acc[9];
        #pragma unroll
        for (int aa = 0; aa < 9; aa++) acc[aa] = 0.f;

        #pragma unroll 4
        for (int i = 0; i < 16; i++) {
            int c = cq*64 + i*4 + cs;
            const float* fp = feat + ((size_t)(n*256 + c)) * 4096
                                   + (fy*8 + ky) * 64 + fx*8;
            float4 f0 = *(const float4*)fp;
            float4 f1 = *(const float4*)(fp + 4);
            #pragma unroll
            for (int aa = 0; aa < 9; aa++) {
                const float* wp = Wreg + ((size_t)(aa*256 + c)) * 64 + ky*8;
                float4 w0 = *(const float4*)wp;
                float4 w1 = *(const float4*)(wp + 4);
                float s = acc[aa];
                s = fmaf(f0.x, w0.x, s); s = fmaf(f0.y, w0.y, s);
                s = fmaf(f0.z, w0.z, s); s = fmaf(f0.w, w0.w, s);
                s = fmaf(f1.x, w1.x, s); s = fmaf(f1.y, w1.y, s);
                s = fmaf(f1.z, w1.z, s); s = fmaf(f1.w, w1.w, s);
                acc[aa] = s;
            }
        }
        #pragma unroll
        for (int aa = 0; aa < 9; aa++) {
            float s = acc[aa];
            #pragma unroll
            for (int off = 16; off; off >>= 1)
                s += __shfl_down_sync(0xffffffffu, s, off);
            if (lane == 0)
                g_regp[cq*4608 + ((n*9 + aa)*8 + fy)*8 + fx] = s;
        }
    }
}

// ---------------------------------------------------------------------------
// Kernel 2: tanh offset + bilinear sample from NHWC feature -> g_roisb
// Block = (k, n, aa-triple). Thread = c (coalesced).
// ---------------------------------------------------------------------------
__global__ __launch_bounds__(256)
void sample_kernel(const float* __restrict__ breg) {
    int k = blockIdx.x;
    int n = blockIdx.y;
    int fy = k >> 3, fx = k & 7;
    int c = threadIdx.x;
    const float* ft = g_featT + (size_t)n * H_ * W_ * C_;
    #pragma unroll
    for (int ai = 0; ai < 3; ai++) {
        int aa = blockIdx.z * 3 + ai;
        int ridx = ((n*9 + aa)*8 + fy)*8 + fx;
        float rg = g_regp[ridx] + g_regp[4608 + ridx]
                 + g_regp[2*4608 + ridx] + g_regp[3*4608 + ridx] + breg[aa];
        float d  = 0.8f * tanhf(rg);
        float pxx = 3.5f + 8.f*fx + d;
        float pyy = 3.5f + 8.f*fy + d;
        float x0f = floorf(pxx), y0f = floorf(pyy);
        float wx = pxx - x0f, wy = pyy - y0f;
        int x0 = min(max((int)x0f, 0), 63);
        int x1 = min(x0 + 1, 63);
        int y0 = min(max((int)y0f, 0), 63);
        int y1 = min(y0 + 1, 63);
        float v00 = ft[(size_t)(y0*64 + x0)*256 + c];
        float v01 = ft[(size_t)(y0*64 + x1)*256 + c];
        float v10 = ft[(size_t)(y1*64 + x0)*256 + c];
        float v11 = ft[(size_t)(y1*64 + x1)*256 + c];
        float val = v00*(1.f-wx)*(1.f-wy) + v01*wx*(1.f-wy)
                  + v10*(1.f-wx)*wy       + v11*wx*wy;
        g_roisb[((size_t)(aa*8 + n)*64 + k)*256 + c] = val;
    }
}

// ---------------------------------------------------------------------------
// Kernel 3: rois_to_rois.  Group (n,aa,c): vectors a[64], b[64] over k,
// out_j = b_j + (sum_i a_i 2^{a'_i b_j - m'})/(sum_i 2^{a'_i b_j - m'}) * ln2
// with a' = a*log2(e), m' = max(b_j a'max, b_j a'min) (exact max, folded in FFMA).
// Grid: (jq 0..3, g 0..71). Thread = c. a' in 64 regs; 16 b_j preloaded.
// ---------------------------------------------------------------------------
__global__ __launch_bounds__(256, 2)
void roisB_kernel(const float* __restrict__ Ain, const float* __restrict__ Bin,
                  float* __restrict__ Out) {
    int g  = blockIdx.y;   // aa*8 + n
    int jq = blockIdx.x;   // quarter of j
    int c  = threadIdx.x;
    const float* Ab = Ain + (size_t)g*64*256 + c;
    const float* Bb = Bin + (size_t)g*64*256 + c;
    float*       Ob = Out + (size_t)g*64*256 + c;

    float bjv[16];
    #pragma unroll
    for (int jj = 0; jj < 16; jj++)
        bjv[jj] = Bb[(jq*16 + jj)*256];

    float ap[64];
    float amax = -1e30f, amin = 1e30f;
    #pragma unroll
    for (int k = 0; k < 64; k++) {
        float v = Ab[k*256] * 1.4426950408889634f;  // a * log2(e)
        ap[k] = v;
        amax = fmaxf(amax, v);
        amin = fminf(amin, v);
    }

    #pragma unroll 1
    for (int jj = 0; jj < 16; jj++) {
        float bj = bjv[jj];
        float mm = fmaxf(bj*amax, bj*amin);   // exact max_i a'_i*bj
        float nmm = -mm;
        float s = 0.f, t = 0.f;
        #pragma unroll
        for (int i = 0; i < 64; i++) {
            float p = fmaf(ap[i], bj, nmm);   // <= 0 always
            float e;
            asm("ex2.approx.f32 %0, %1;" : "=f"(e) : "f"(p));
            s += e;
            t = fmaf(ap[i], e, t);
        }
        Ob[(jq*16 + jj)*256] = bj + __fdividef(t * 0.6931471805599453f, s);
    }
}

// ---------------------------------------------------------------------------
// Launch sequence (default stream, graph-capturable; no sync, no alloc)
// ---------------------------------------------------------------------------
extern "C" void kernel_launch(void* const* d_in, const int* in_sizes, int n_in,
                              void* d_out, int out_size) {
    const float* rois_a = (const float*)d_in[1];
    const float* feat   = (const float*)d_in[2];
    const float* rois_c = (const float*)d_in[3];
    const float* Wreg   = (const float*)d_in[4];
    const float* breg   = (const float*)d_in[5];
    float* out = (float*)d_out;

    void *p_roisb = nullptr, *p_tmp = nullptr;
    cudaGetSymbolAddress(&p_roisb, g_roisb);
    cudaGetSymbolAddress(&p_tmp, g_tmp);

    fused_tc_kernel<<<8448, 256>>>(feat, Wreg);
    sample_kernel<<<dim3(64, 8, 3), 256>>>(breg);
    roisB_kernel<<<dim3(4, 72), 256>>>(rois_a, (const float*)p_roisb, (float*)p_tmp);
    roisB_kernel<<<dim3(4, 72), 256>>>((const float*)p_tmp, rois_c, out);
}

// round 4
// speedup vs baseline: 1.7434x; 1.7434x over previous
#include <cuda_runtime.h>
#include <cstdint>
#include <cstddef>

// Problem constants (fixed by setup_inputs)
#define N_ 8
#define C_ 256
#define H_ 64
#define W_ 64
#define A_ 9
#define BS_ 8
#define F_ 8
#define K_ 64
#define M_ (A_*N_*K_)   // 4608

// Scratch (static device globals; no runtime allocation)
__device__ float g_reg[N_*A_*F_*F_];           // 4608 conv outputs
__device__ float g_featT[(size_t)N_*H_*W_*C_]; // NHWC transposed feature
__device__ float g_roisb[(size_t)M_*C_];       // sampled rois_feature_b
__device__ float g_tmp[(size_t)M_*C_];         // intermediate rois output

// ---------------------------------------------------------------------------
// Kernel 1: zero the conv accumulator (atomics accumulate into it each launch)
// ---------------------------------------------------------------------------
__global__ void zero_reg_kernel() {
    int i = blockIdx.x * blockDim.x + threadIdx.x;
    if (i < N_*A_*F_*F_) g_reg[i] = 0.f;
}

// ---------------------------------------------------------------------------
// Kernel 2: NCHW -> NHWC transpose of feature_b (for coalesced bilinear gathers)
// ---------------------------------------------------------------------------
__global__ void transpose_kernel(const float* __restrict__ feat) {
    __shared__ float tile[32][33];
    int n = blockIdx.z, ct = blockIdx.y, hwt = blockIdx.x;
    int tx = threadIdx.x, ty = threadIdx.y;
    const float* src = feat + (size_t)n * C_ * H_ * W_;
    float* dst = g_featT + (size_t)n * H_ * W_ * C_;
    #pragma unroll
    for (int r = 0; r < 4; r++) {
        int c = ct*32 + ty + r*8;
        tile[ty + r*8][tx] = src[(size_t)c * 4096 + hwt*32 + tx];
    }
    __syncthreads();
    #pragma unroll
    for (int r = 0; r < 4; r++) {
        int hw = hwt*32 + ty + r*8;
        dst[(size_t)hw * 256 + ct*32 + tx] = tile[tx][ty + r*8];
    }
}

// ---------------------------------------------------------------------------
// Kernel 3: stride-8 8x8 "VALID" conv (R1 smem-staged version — coalesced)
// Block = (cc in 0..7 [32-channel slice], fyh in 0..1, n). 256 threads =
// (ky 0..7) x (cl 0..31). W slice + one fy patch band staged in smem.
// ---------------------------------------------------------------------------
#define WS 68                      // padded W row stride (floats)
#define PS 516                     // padded patch per-channel stride (floats)
#define CONV_SMEM ((9*32*WS + 32*PS) * 4)

__global__ __launch_bounds__(256, 1)
void conv_kernel(const float* __restrict__ feat, const float* __restrict__ Wreg) {
    extern __shared__ float sm[];
    float* Wsl   = sm;               // [9][32][WS]
    float* patch = sm + 9*32*WS;     // [32][PS] (8 rows x 64 cols used)
    int cc  = blockIdx.x;
    int fyh = blockIdx.y;
    int n   = blockIdx.z;
    int tid = threadIdx.x;
    int ky = tid >> 5, cl = tid & 31;

    // Stage W slice: 9 * 32 * 64 floats, coalesced float4 loads
    #pragma unroll
    for (int it = 0; it < 18; it++) {
        int idx4 = it*256 + tid;       // 0..4607 float4s
        int aa  = idx4 >> 9;
        int rem = idx4 & 511;
        int clw = rem >> 4;
        int p4  = rem & 15;
        float4 v = *(const float4*)(Wreg + ((size_t)(aa*256 + cc*32 + clw)*64 + p4*4));
        *(float4*)(Wsl + (aa*32 + clw)*WS + p4*4) = v;
    }
    __syncthreads();

    for (int fy = fyh*4; fy < fyh*4 + 4; fy++) {
        // Stage patch band: 32c x 8 rows x 64 cols, coalesced float4
        #pragma unroll
        for (int it = 0; it < 16; it++) {
            int idx4 = it*256 + tid;   // 0..4095
            int clp = idx4 >> 7;
            int rem = idx4 & 127;
            int kyp = rem >> 4;
            int x4  = rem & 15;
            float4 v = *(const float4*)(feat +
                (((size_t)(n*256 + cc*32 + clp)*64 + fy*8 + kyp)*64 + x4*4));
            *(float4*)(patch + clp*PS + kyp*64 + x4*4) = v;
        }
        __syncthreads();

        // Each thread owns (cl, ky): its 64-pixel row band in registers
        float px[64];
        #pragma unroll
        for (int x4 = 0; x4 < 16; x4++) {
            float4 v = *(const float4*)(patch + cl*PS + ky*64 + x4*4);
            px[x4*4+0] = v.x; px[x4*4+1] = v.y; px[x4*4+2] = v.z; px[x4*4+3] = v.w;
        }
        #pragma unroll
        for (int aa = 0; aa < 9; aa++) {
            float w[8];
            float4 v0 = *(const float4*)(Wsl + (aa*32 + cl)*WS + ky*8);
            float4 v1 = *(const float4*)(Wsl + (aa*32 + cl)*WS + ky*8 + 4);
            w[0]=v0.x; w[1]=v0.y; w[2]=v0.z; w[3]=v0.w;
            w[4]=v1.x; w[5]=v1.y; w[6]=v1.z; w[7]=v1.w;
            #pragma unroll
            for (int fx = 0; fx < 8; fx++) {
                float acc = 0.f;
                #pragma unroll
                for (int kx = 0; kx < 8; kx++)
                    acc = fmaf(px[fx*8 + kx], w[kx], acc);
                #pragma unroll
                for (int off = 16; off; off >>= 1)
                    acc += __shfl_down_sync(0xffffffffu, acc, off);
                if (cl == 0)
                    atomicAdd(&g_reg[((n*9 + aa)*8 + fy)*8 + fx], acc);
            }
        }
        __syncthreads();
    }
}

// ---------------------------------------------------------------------------
// Kernel 4: tanh offset + bilinear sample from NHWC feature -> g_roisb
// Block = (k, n, aa-triple). Thread = c (coalesced).
// ---------------------------------------------------------------------------
__global__ __launch_bounds__(256)
void sample_kernel(const float* __restrict__ breg) {
    int k = blockIdx.x;
    int n = blockIdx.y;
    int fy = k >> 3, fx = k & 7;
    int c = threadIdx.x;
    const float* ft = g_featT + (size_t)n * H_ * W_ * C_;
    #pragma unroll
    for (int ai = 0; ai < 3; ai++) {
        int aa = blockIdx.z * 3 + ai;
        float rg = g_reg[((n*9 + aa)*8 + fy)*8 + fx] + breg[aa];
        float d  = 0.8f * tanhf(rg);
        float pxx = 3.5f + 8.f*fx + d;
        float pyy = 3.5f + 8.f*fy + d;
        float x0f = floorf(pxx), y0f = floorf(pyy);
        float wx = pxx - x0f, wy = pyy - y0f;
        int x0 = min(max((int)x0f, 0), 63);
        int x1 = min(x0 + 1, 63);
        int y0 = min(max((int)y0f, 0), 63);
        int y1 = min(y0 + 1, 63);
        float v00 = ft[(size_t)(y0*64 + x0)*256 + c];
        float v01 = ft[(size_t)(y0*64 + x1)*256 + c];
        float v10 = ft[(size_t)(y1*64 + x0)*256 + c];
        float v11 = ft[(size_t)(y1*64 + x1)*256 + c];
        float val = v00*(1.f-wx)*(1.f-wy) + v01*wx*(1.f-wy)
                  + v10*(1.f-wx)*wy       + v11*wx*wy;
        g_roisb[((size_t)(aa*8 + n)*64 + k)*256 + c] = val;
    }
}

// ---------------------------------------------------------------------------
// Kernel 5: rois_to_rois with f16x2 EX2 + packed f32x2 accumulation.
// out_j = b_j + (sum_i a_i 2^{p_i})/(sum_i 2^{p_i}) * ln2, p_i = a'_i b_j - m'
// a' = a*log2(e); m' = max(b_j a'max, b_j a'min) folds exact max into the FMA2.
// Per i-pair: FMA2(p) -> F2FP pack -> MUFU.EX2.f16x2 -> 2x F2F unpack ->
// ADD2(s) + FMA2(t).  MUFU ops halved vs f32 path.
// ---------------------------------------------------------------------------
__global__ __launch_bounds__(256, 2)
void roisB_kernel(const float* __restrict__ Ain, const float* __restrict__ Bin,
                  float* __restrict__ Out) {
    int g  = blockIdx.y;   // aa*8 + n
    int jq = blockIdx.x;   // quarter of j
    int c  = threadIdx.x;
    const float* Ab = Ain + (size_t)g*64*256 + c;
    const float* Bb = Bin + (size_t)g*64*256 + c;
    float*       Ob = Out + (size_t)g*64*256 + c;

    float bjv[16];
    #pragma unroll
    for (int jj = 0; jj < 16; jj++)
        bjv[jj] = Bb[(jq*16 + jj)*256];

    unsigned long long ap2[32];
    float amax = -1e30f, amin = 1e30f;
    #pragma unroll
    for (int k = 0; k < 32; k++) {
        float v0 = Ab[(2*k  )*256] * 1.4426950408889634f;
        float v1 = Ab[(2*k+1)*256] * 1.4426950408889634f;
        amax = fmaxf(amax, fmaxf(v0, v1));
        amin = fminf(amin, fminf(v0, v1));
        ap2[k] = ((unsigned long long)__float_as_uint(v1) << 32)
               |  (unsigned long long)__float_as_uint(v0);
    }

    #pragma unroll 1
    for (int jj = 0; jj < 16; jj++) {
        float bj  = bjv[jj];
        float mm  = fmaxf(bj*amax, bj*amin);   // exact max_i a'_i*bj
        float nmm = -mm;
        unsigned long long bj2 = ((unsigned long long)__float_as_uint(bj)  << 32)
                               |  (unsigned long long)__float_as_uint(bj);
        unsigned long long nm2 = ((unsigned long long)__float_as_uint(nmm) << 32)
                               |  (unsigned long long)__float_as_uint(nmm);
        unsigned long long s2 = 0ull, t2 = 0ull;   // packed f32x2 {0,0}
        #pragma unroll
        for (int i = 0; i < 32; i++) {
            unsigned long long p2, e2;
            unsigned int eh;
            asm("fma.rn.f32x2 %0, %1, %2, %3;"
                : "=l"(p2) : "l"(ap2[i]), "l"(bj2), "l"(nm2));
            asm("{\n\t.reg .b32 lo, hi;\n\t"
                "mov.b64 {lo, hi}, %1;\n\t"
                "cvt.rn.f16x2.f32 %0, hi, lo;\n\t}"
                : "=r"(eh) : "l"(p2));
            asm("ex2.approx.f16x2 %0, %0;" : "+r"(eh));
            asm("{\n\t.reg .f16 l16, h16;\n\t.reg .f32 lf, hf;\n\t"
                "mov.b32 {l16, h16}, %1;\n\t"
                "cvt.f32.f16 lf, l16;\n\t"
                "cvt.f32.f16 hf, h16;\n\t"
                "mov.b64 %0, {lf, hf};\n\t}"
                : "=l"(e2) : "r"(eh));
            asm("add.rn.f32x2 %0, %0, %1;" : "+l"(s2) : "l"(e2));
            asm("fma.rn.f32x2 %0, %1, %2, %0;" : "+l"(t2) : "l"(ap2[i]), "l"(e2));
        }
        float s = __uint_as_float((unsigned)s2) + __uint_as_float((unsigned)(s2 >> 32));
        float t = __uint_as_float((unsigned)t2) + __uint_as_float((unsigned)(t2 >> 32));
        Ob[(jq*16 + jj)*256] = bj + __fdividef(t * 0.6931471805599453f, s);
    }
}

// ---------------------------------------------------------------------------
// Launch sequence (default stream, graph-capturable; no sync, no alloc)
// ---------------------------------------------------------------------------
extern "C" void kernel_launch(void* const* d_in, const int* in_sizes, int n_in,
                              void* d_out, int out_size) {
    const float* rois_a = (const float*)d_in[1];
    const float* feat   = (const float*)d_in[2];
    const float* rois_c = (const float*)d_in[3];
    const float* Wreg   = (const float*)d_in[4];
    const float* breg   = (const float*)d_in[5];
    float* out = (float*)d_out;

    cudaFuncSetAttribute(conv_kernel,
                         cudaFuncAttributeMaxDynamicSharedMemorySize, CONV_SMEM);

    void *p_roisb = nullptr, *p_tmp = nullptr;
    cudaGetSymbolAddress(&p_roisb, g_roisb);
    cudaGetSymbolAddress(&p_tmp, g_tmp);

    zero_reg_kernel<<<18, 256>>>();
    transpose_kernel<<<dim3(128, 8, 8), dim3(32, 8)>>>(feat);
    conv_kernel<<<dim3(8, 2, 8), 256, CONV_SMEM>>>(feat, Wreg);
    sample_kernel<<<dim3(64, 8, 3), 256>>>(breg);
    roisB_kernel<<<dim3(4, 72), 256>>>(rois_a, (const float*)p_roisb, (float*)p_tmp);
    roisB_kernel<<<dim3(4, 72), 256>>>((const float*)p_tmp, rois_c, out);
}